// round 13
// baseline (speedup 1.0000x reference)
#include <cuda_runtime.h>
#include <cuda_bf16.h>
#include <cstdint>
#include <math.h>

#define LSEQ 1024
#define DMODEL 1024
#define NHEADS 16
#define DHEAD 64
#define NLAYER 3
#define DFF 4096
#define NCLS 7

// ===================== helpers =====================
__device__ __forceinline__ uint32_t smem_to_u32(const void* p) {
    uint32_t a;
    asm("{ .reg .u64 t; cvta.to.shared.u64 t, %1; cvt.u32.u64 %0, t; }" : "=r"(a) : "l"(p));
    return a;
}
__device__ __forceinline__ void ldsm4(uint32_t* r, uint32_t addr) {
    asm volatile("ldmatrix.sync.aligned.m8n8.x4.shared.b16 {%0,%1,%2,%3}, [%4];"
        : "=r"(r[0]), "=r"(r[1]), "=r"(r[2]), "=r"(r[3]) : "r"(addr));
}
__device__ __forceinline__ void mma_bf16(float* d, const uint32_t* a, uint32_t b0, uint32_t b1) {
    asm volatile(
        "mma.sync.aligned.m16n8k16.row.col.f32.bf16.bf16.f32 "
        "{%0,%1,%2,%3}, {%4,%5,%6,%7}, {%8,%9}, {%0,%1,%2,%3};"
        : "+f"(d[0]), "+f"(d[1]), "+f"(d[2]), "+f"(d[3])
        : "r"(a[0]), "r"(a[1]), "r"(a[2]), "r"(a[3]), "r"(b0), "r"(b1));
}
#define CP_ASYNC_CG(dst, src) \
    asm volatile("cp.async.cg.shared.global [%0], [%1], 16;" :: "r"(dst), "l"(src))
#define CP_COMMIT() asm volatile("cp.async.commit_group;" ::: "memory")
#define CP_WAIT0()  asm volatile("cp.async.wait_group 0;" ::: "memory")

__device__ __forceinline__ void split_bf16(float v, __nv_bfloat16& h, __nv_bfloat16& l) {
    h = __float2bfloat16_rn(v);
    l = __float2bfloat16_rn(v - __bfloat162float(h));
}

// ===================== scratch (static device memory) =====================
__device__ float g_x[3 * LSEQ * DMODEL];
__device__ float g_qkv[3 * LSEQ * 3 * DMODEL];
__device__ float g_t2[3 * LSEQ * DMODEL];
__device__ float g_t1f[2 * LSEQ * DMODEL];      // fusion GEMM fp32 outputs
__device__ float g_sc[2 * LSEQ];
__device__ float g_sp[LSEQ * DMODEL];
__device__ float g_fo[LSEQ * DMODEL];
// bf16 hi/lo activations
__device__ __nv_bfloat16 g_xh[3 * LSEQ * DMODEL],  g_xl[3 * LSEQ * DMODEL];
__device__ __nv_bfloat16 g_ah[3 * LSEQ * DMODEL],  g_al[3 * LSEQ * DMODEL];   // attn out
__device__ __nv_bfloat16 g_t1h[3 * LSEQ * DFF],    g_t1l[3 * LSEQ * DFF];     // ff1 out
__device__ __nv_bfloat16 g_sph[LSEQ * DMODEL],     g_spl[LSEQ * DMODEL];
// transposed bf16 hi/lo weights: [batch][N][K]
__device__ __nv_bfloat16 g_wqkvT_h[9 * 3072 * 1024], g_wqkvT_l[9 * 3072 * 1024];
__device__ __nv_bfloat16 g_woT_h[9 * 1024 * 1024],   g_woT_l[9 * 1024 * 1024];
__device__ __nv_bfloat16 g_wf1T_h[9 * 4096 * 1024],  g_wf1T_l[9 * 4096 * 1024];
__device__ __nv_bfloat16 g_wf2T_h[9 * 1024 * 4096],  g_wf2T_l[9 * 1024 * 4096];
__device__ __nv_bfloat16 g_f1wT_h[1024 * 1024], g_f1wT_l[1024 * 1024];
__device__ __nv_bfloat16 g_f2wT_h[1024 * 1024], g_f2wT_l[1024 * 1024];

// ===================== weight transpose + hi/lo split =====================
__global__ void __launch_bounds__(256) transpose_split_kernel(
    const float* __restrict__ src, __nv_bfloat16* __restrict__ hi,
    __nv_bfloat16* __restrict__ lo, int K, int N)
{
    __shared__ float t[32][33];
    long long b = blockIdx.z;
    src += b * (long long)K * N;
    hi  += b * (long long)K * N;
    lo  += b * (long long)K * N;
    int k0 = blockIdx.y * 32, n0 = blockIdx.x * 32;
    int tx = threadIdx.x, ty = threadIdx.y;   // 32 x 8
#pragma unroll
    for (int i = 0; i < 4; i++)
        t[ty + i * 8][tx] = src[(long long)(k0 + ty + i * 8) * N + n0 + tx];
    __syncthreads();
#pragma unroll
    for (int i = 0; i < 4; i++) {
        float v = t[tx][ty + i * 8];
        __nv_bfloat16 h, l; split_bf16(v, h, l);
        long long o = (long long)(n0 + ty + i * 8) * K + k0 + tx;
        hi[o] = h; lo[o] = l;
    }
}

// ===================== HMMA GEMM: all-bf16 operands, full cp.async pipeline ==========
// C[z] = A[z] @ B[z]^T; A [M,K] hi/lo bf16, B [N,K] hi/lo bf16; + bias.
// mode: bit0 = relu, bit1 = write fp32 C, bit2 = write bf16 hi/lo (Ch/Cl).
// CTA tile 128x128, K-chunk 32, double-buffered. 256 threads (8 warps = 2M x 4N).
// SMEM/buffer: Ah@0 Al@10240 Bh@20480 Bl@30720, 80B pitch, 128 rows x 64B data.
#define GEMM_SMEM_BYTES (2 * 40960)
__global__ void __launch_bounds__(256, 2) hmma_gemm_kernel(
    const __nv_bfloat16* __restrict__ Ah, const __nv_bfloat16* __restrict__ Al, long long aZ,
    const __nv_bfloat16* __restrict__ Bh, const __nv_bfloat16* __restrict__ Bl, long long bZ,
    const float* __restrict__ bias, long long biasZ,
    float* __restrict__ C, __nv_bfloat16* __restrict__ Ch, __nv_bfloat16* __restrict__ Cl,
    long long cZ, int N, int K, int mode)
{
    extern __shared__ char smem[];
    uint32_t sbase = smem_to_u32(smem);
    int tid = threadIdx.x;
    int wid = tid >> 5, lane = tid & 31;
    long long z = blockIdx.z;
    Ah += z * aZ + (long long)blockIdx.y * 128 * K;
    Al += z * aZ + (long long)blockIdx.y * 128 * K;
    Bh += z * bZ + (long long)blockIdx.x * 128 * K;
    Bl += z * bZ + (long long)blockIdx.x * 128 * K;
    long long cOff = z * cZ + (long long)blockIdx.y * 128 * N + blockIdx.x * 128;
    const float* bb = bias + z * biasZ + blockIdx.x * 128;

    int wm = (wid & 1) * 64;
    int wn = (wid >> 1) * 32;

    float acc[4][4][4];
#pragma unroll
    for (int i = 0; i < 4; i++)
#pragma unroll
        for (int j = 0; j < 4; j++)
#pragma unroll
            for (int r = 0; r < 4; r++) acc[i][j][r] = 0.f;

    // 16B-granule indices: e = tid + i*256, r = e>>2 (row), g = e&3 (16B col)
    int r0 = tid >> 2, gb = (tid & 3) << 4;   // byte col, element col = gb>>1

    // prologue: chunk 0 -> buffer 0
    {
        uint32_t d = sbase + (uint32_t)(r0 * 80) + gb;
        const __nv_bfloat16 *sa_h = Ah + (long long)r0 * K + (gb >> 1);
        const __nv_bfloat16 *sa_l = Al + (long long)r0 * K + (gb >> 1);
        const __nv_bfloat16 *sb_h = Bh + (long long)r0 * K + (gb >> 1);
        const __nv_bfloat16 *sb_l = Bl + (long long)r0 * K + (gb >> 1);
#pragma unroll
        for (int i = 0; i < 2; i++) {
            uint32_t dd = d + (uint32_t)(i * 64 * 80);
            long long so = (long long)(i * 64) * K;
            CP_ASYNC_CG(dd,          sa_h + so);
            CP_ASYNC_CG(dd + 10240u, sa_l + so);
            CP_ASYNC_CG(dd + 20480u, sb_h + so);
            CP_ASYNC_CG(dd + 30720u, sb_l + so);
        }
        CP_COMMIT();
    }

    const int nchunks = K >> 5;
    for (int c = 0; c < nchunks; c++) {
        uint32_t bufa = sbase + (uint32_t)((c & 1) * 40960);
        CP_WAIT0();
        __syncthreads();

        // issue chunk c+1 into the other buffer
        if (c + 1 < nchunks) {
            int ce = (c + 1) << 5;
            uint32_t d = sbase + (uint32_t)(((c + 1) & 1) * 40960) + (uint32_t)(r0 * 80) + gb;
            const __nv_bfloat16 *sa_h = Ah + (long long)r0 * K + (gb >> 1) + ce;
            const __nv_bfloat16 *sa_l = Al + (long long)r0 * K + (gb >> 1) + ce;
            const __nv_bfloat16 *sb_h = Bh + (long long)r0 * K + (gb >> 1) + ce;
            const __nv_bfloat16 *sb_l = Bl + (long long)r0 * K + (gb >> 1) + ce;
#pragma unroll
            for (int i = 0; i < 2; i++) {
                uint32_t dd = d + (uint32_t)(i * 64 * 80);
                long long so = (long long)(i * 64) * K;
                CP_ASYNC_CG(dd,          sa_h + so);
                CP_ASYNC_CG(dd + 10240u, sa_l + so);
                CP_ASYNC_CG(dd + 20480u, sb_h + so);
                CP_ASYNC_CG(dd + 30720u, sb_l + so);
            }
            CP_COMMIT();
        }

        // compute chunk c
        int lrow = lane & 15;
        int lcol = (lane >> 4) << 4;
#pragma unroll
        for (int ks = 0; ks < 2; ks++) {
            uint32_t bhf[2][4], blf[2][4];
#pragma unroll
            for (int bf = 0; bf < 2; bf++) {
                uint32_t bd = bufa + 20480 + (uint32_t)((wn + bf * 16 + lrow) * 80 + ks * 32 + lcol);
                ldsm4(bhf[bf], bd);
                ldsm4(blf[bf], bd + 10240);
            }
#pragma unroll
            for (int mf = 0; mf < 4; mf++) {
                uint32_t ah[4], al[4];
                uint32_t ad = bufa + (uint32_t)((wm + mf * 16 + lrow) * 80 + ks * 32 + lcol);
                ldsm4(ah, ad);
                ldsm4(al, ad + 10240);
#pragma unroll
                for (int nf = 0; nf < 4; nf++) {
                    int bf = nf >> 1, hf = nf & 1;
                    mma_bf16(acc[mf][nf], ah, bhf[bf][hf], bhf[bf][hf + 2]);
                    mma_bf16(acc[mf][nf], ah, blf[bf][hf], blf[bf][hf + 2]);
                    mma_bf16(acc[mf][nf], al, bhf[bf][hf], bhf[bf][hf + 2]);
                }
            }
        }
        __syncthreads();
    }

    // ---- epilogue ----
    int lm = lane >> 2, ln = (lane & 3) << 1;
#pragma unroll
    for (int mf = 0; mf < 4; mf++) {
#pragma unroll
        for (int nf = 0; nf < 4; nf++) {
            int row = wm + mf * 16 + lm;
            int col = wn + nf * 8 + ln;
            float b0 = bb[col], b1 = bb[col + 1];
            float v00 = acc[mf][nf][0] + b0, v01 = acc[mf][nf][1] + b1;
            float v10 = acc[mf][nf][2] + b0, v11 = acc[mf][nf][3] + b1;
            if (mode & 1) {
                v00 = fmaxf(v00, 0.f); v01 = fmaxf(v01, 0.f);
                v10 = fmaxf(v10, 0.f); v11 = fmaxf(v11, 0.f);
            }
            long long o0 = cOff + (long long)row * N + col;
            long long o1 = cOff + (long long)(row + 8) * N + col;
            if (mode & 2) {
                *(float2*)(C + o0) = make_float2(v00, v01);
                *(float2*)(C + o1) = make_float2(v10, v11);
            }
            if (mode & 4) {
                __nv_bfloat16 h0, l0, h1, l1;
                split_bf16(v00, h0, l0); split_bf16(v01, h1, l1);
                *(__nv_bfloat162*)(Ch + o0) = __nv_bfloat162(h0, h1);
                *(__nv_bfloat162*)(Cl + o0) = __nv_bfloat162(l0, l1);
                split_bf16(v10, h0, l0); split_bf16(v11, h1, l1);
                *(__nv_bfloat162*)(Ch + o1) = __nv_bfloat162(h0, h1);
                *(__nv_bfloat162*)(Cl + o1) = __nv_bfloat162(l0, l1);
            }
        }
    }
}

// ===================== x = src + PE; writes fp32 x (3 copies) + bf16 hi/lo ===========
__global__ void add_pe_kernel(const float* __restrict__ src, float* __restrict__ x,
                              __nv_bfloat16* __restrict__ xh, __nv_bfloat16* __restrict__ xl)
{
    int idx = blockIdx.x * 256 + threadIdx.x;
    int row = idx >> 10;
    int d   = idx & 1023;
    float e = (float)(d & ~1) / 1024.0f;
    float denom = powf(10000.0f, e);
    float ang = (float)row / denom;
    float pe = (d & 1) ? cosf(ang) : sinf(ang);
    float v = src[idx] + pe;
    __nv_bfloat16 h, l; split_bf16(v, h, l);
    const int LD = LSEQ * DMODEL;
#pragma unroll
    for (int b = 0; b < 3; b++) {
        x[idx + b * LD] = v;
        xh[idx + b * LD] = h;
        xl[idx + b * LD] = l;
    }
}

// ===================== windowed flash attention; writes bf16 hi/lo output ===========
__global__ void __launch_bounds__(256) attn_kernel(
    const float* __restrict__ qkv,
    __nv_bfloat16* __restrict__ oh, __nv_bfloat16* __restrict__ ol,
    const int* __restrict__ utt, const int* __restrict__ spkm,
    const int* __restrict__ winp)
{
    __shared__ __align__(16) float Qs[64][68];
    __shared__ __align__(16) float Ks[32][68];
    __shared__ __align__(16) float Vs[32][68];
    __shared__ float Ps[64][33];
    __shared__ int spq[64], utq[64], spkk[32], utk[32];

    int tid = threadIdx.x;
    int q0  = blockIdx.x * 64;
    int h   = blockIdx.y;
    int b   = blockIdx.z;
    int W   = winp[0];
    long long base = (long long)b * LSEQ * 3072;

#pragma unroll
    for (int i = 0; i < 4; i++) {
        int g = tid + i * 256;
        int r = g >> 4, c4 = (g & 15) * 4;
        float4 q = *(const float4*)(qkv + base + (long long)(q0 + r) * 3072 + h * 64 + c4);
        q.x *= 0.125f; q.y *= 0.125f; q.z *= 0.125f; q.w *= 0.125f;
        *(float4*)&Qs[r][c4] = q;
    }
    if (tid < 64) { spq[tid] = spkm[q0 + tid]; utq[tid] = utt[q0 + tid]; }

    int tq = tid >> 2;
    int part = tid & 3;
    int i_row = q0 + tq;

    float m = -1e30f, lsum = 0.f;
    float acc[16];
#pragma unroll
    for (int d = 0; d < 16; d++) acc[d] = 0.f;

    int jlo = q0 - W; if (jlo < 0) jlo = 0;
    int jhi = q0 + 63 + W; if (jhi > LSEQ - 1) jhi = LSEQ - 1;

    for (int j0 = jlo & ~31; j0 <= jhi; j0 += 32) {
        __syncthreads();
#pragma unroll
        for (int i = 0; i < 2; i++) {
            int g = tid + i * 256;
            int r = g >> 4, c4 = (g & 15) * 4;
            int j = j0 + r;
            float4 kv = make_float4(0.f, 0.f, 0.f, 0.f);
            float4 vv = make_float4(0.f, 0.f, 0.f, 0.f);
            if (j < LSEQ) {
                kv = *(const float4*)(qkv + base + (long long)j * 3072 + 1024 + h * 64 + c4);
                vv = *(const float4*)(qkv + base + (long long)j * 3072 + 2048 + h * 64 + c4);
            }
            *(float4*)&Ks[r][c4] = kv;
            *(float4*)&Vs[r][c4] = vv;
        }
        if (tid < 32) {
            int j = j0 + tid;
            spkk[tid] = (j < LSEQ) ? spkm[j] : -12345;
            utk[tid]  = (j < LSEQ) ? utt[j]  : 0;
        }
        __syncthreads();

        float s[8];
#pragma unroll
        for (int kk = 0; kk < 8; kk++) s[kk] = 0.f;
#pragma unroll
        for (int c0 = 0; c0 < 64; c0 += 16) {
            float q[16];
#pragma unroll
            for (int c = 0; c < 16; c += 4) {
                float4 t = *(const float4*)&Qs[tq][c0 + c];
                q[c] = t.x; q[c + 1] = t.y; q[c + 2] = t.z; q[c + 3] = t.w;
            }
#pragma unroll
            for (int kk = 0; kk < 8; kk++) {
                int key = kk * 4 + part;
#pragma unroll
                for (int c = 0; c < 16; c += 4) {
                    float4 t = *(const float4*)&Ks[key][c0 + c];
                    s[kk] += q[c] * t.x + q[c + 1] * t.y + q[c + 2] * t.z + q[c + 3] * t.w;
                }
            }
        }

        int mu = utq[tq], ms = spq[tq];
        float cmax = -3e30f;
#pragma unroll
        for (int kk = 0; kk < 8; kk++) {
            int key = kk * 4 + part;
            int j = j0 + key;
            int d = j - i_row;
            bool ok = (j < LSEQ) && (mu != 0) && (utk[key] != 0) && (d <= W) && (d >= -W);
            if (b == 1) ok = ok && (ms == spkk[key]);
            if (b == 2) ok = ok && ((ms != spkk[key]) || (d == 0));
            if (!ok) s[kk] = -2e30f;
            cmax = fmaxf(cmax, s[kk]);
        }
        cmax = fmaxf(cmax, __shfl_xor_sync(0xffffffffu, cmax, 1));
        cmax = fmaxf(cmax, __shfl_xor_sync(0xffffffffu, cmax, 2));
        float newm = fmaxf(m, cmax);
        float alpha = __expf(m - newm);
        float psum = 0.f;
#pragma unroll
        for (int kk = 0; kk < 8; kk++) {
            float p = __expf(s[kk] - newm);
            Ps[tq][kk * 4 + part] = p;
            psum += p;
        }
        psum += __shfl_xor_sync(0xffffffffu, psum, 1);
        psum += __shfl_xor_sync(0xffffffffu, psum, 2);
        lsum = lsum * alpha + psum;
        m = newm;
#pragma unroll
        for (int d = 0; d < 16; d++) acc[d] *= alpha;
        __syncwarp();
        if (psum > 0.f) {
#pragma unroll
            for (int key = 0; key < 32; key++) {
                float p = Ps[tq][key];
#pragma unroll
                for (int c = 0; c < 16; c += 4) {
                    float4 v = *(const float4*)&Vs[key][part * 16 + c];
                    acc[c]     += p * v.x; acc[c + 1] += p * v.y;
                    acc[c + 2] += p * v.z; acc[c + 3] += p * v.w;
                }
            }
        }
    }

    float inv = (lsum > 0.f) ? 1.f / lsum : 0.f;
    long long ob = ((long long)b * LSEQ + i_row) * 1024 + h * 64 + part * 16;
#pragma unroll
    for (int c = 0; c < 16; c += 2) {
        __nv_bfloat16 h0, l0, h1, l1;
        split_bf16(acc[c] * inv, h0, l0);
        split_bf16(acc[c + 1] * inv, h1, l1);
        *(__nv_bfloat162*)(oh + ob + c) = __nv_bfloat162(h0, h1);
        *(__nv_bfloat162*)(ol + ob + c) = __nv_bfloat162(l0, l1);
    }
}

// ===================== fused residual-add + LayerNorm; fp32 + hi/lo out ==============
__global__ void __launch_bounds__(256) add_ln_kernel(
    float* __restrict__ x, __nv_bfloat16* __restrict__ xh, __nv_bfloat16* __restrict__ xl,
    const float* __restrict__ r,
    const float* __restrict__ g, const float* __restrict__ bta, int layer)
{
    __shared__ float s1[8], s2[8];
    int row = blockIdx.x;
    int z = row >> 10;
    const float* gg = g   + ((long long)z * NLAYER + layer) * 1024;
    const float* bb = bta + ((long long)z * NLAYER + layer) * 1024;
    float* xr = x + (long long)row * 1024;
    const float* rr = r + (long long)row * 1024;
    int tid = threadIdx.x;

    float4 xv = *(const float4*)(xr + tid * 4);
    float4 rv = *(const float4*)(rr + tid * 4);
    float v0 = xv.x + rv.x, v1 = xv.y + rv.y, v2 = xv.z + rv.z, v3 = xv.w + rv.w;
    float sum = v0 + v1 + v2 + v3;
    float sq  = v0 * v0 + v1 * v1 + v2 * v2 + v3 * v3;
#pragma unroll
    for (int o = 16; o; o >>= 1) {
        sum += __shfl_xor_sync(0xffffffffu, sum, o);
        sq  += __shfl_xor_sync(0xffffffffu, sq,  o);
    }
    if ((tid & 31) == 0) { s1[tid >> 5] = sum; s2[tid >> 5] = sq; }
    __syncthreads();
    if (tid < 32) {
        sum = (tid < 8) ? s1[tid] : 0.f;
        sq  = (tid < 8) ? s2[tid] : 0.f;
#pragma unroll
        for (int o = 4; o; o >>= 1) {
            sum += __shfl_xor_sync(0xffffffffu, sum, o);
            sq  += __shfl_xor_sync(0xffffffffu, sq,  o);
        }
        if (tid == 0) { s1[0] = sum; s2[0] = sq; }
    }
    __syncthreads();
    float mean = s1[0] * (1.f / 1024.f);
    float var  = s2[0] * (1.f / 1024.f) - mean * mean;
    float rstd = rsqrtf(var + 1e-5f);
    float4 gv = *(const float4*)(gg + tid * 4);
    float4 bv = *(const float4*)(bb + tid * 4);
    float4 o;
    o.x = (v0 - mean) * rstd * gv.x + bv.x;
    o.y = (v1 - mean) * rstd * gv.y + bv.y;
    o.z = (v2 - mean) * rstd * gv.z + bv.z;
    o.w = (v3 - mean) * rstd * gv.w + bv.w;
    *(float4*)(xr + tid * 4) = o;
    __nv_bfloat16 h0, l0, h1, l1;
    long long ob = (long long)row * 1024 + tid * 4;
    split_bf16(o.x, h0, l0); split_bf16(o.y, h1, l1);
    *(__nv_bfloat162*)(xh + ob) = __nv_bfloat162(h0, h1);
    *(__nv_bfloat162*)(xl + ob) = __nv_bfloat162(l0, l1);
    split_bf16(o.z, h0, l0); split_bf16(o.w, h1, l1);
    *(__nv_bfloat162*)(xh + ob + 2) = __nv_bfloat162(h0, h1);
    *(__nv_bfloat162*)(xl + ob + 2) = __nv_bfloat162(l0, l1);
}

// ===================== fusion attention =====================
__global__ void __launch_bounds__(256) fuse_score_kernel(
    const float* __restrict__ t, const float* __restrict__ v, float* __restrict__ s)
{
    __shared__ float red[8];
    int l = blockIdx.x, k = blockIdx.y, tid = threadIdx.x;
    const float* row = t + ((long long)k * LSEQ + l) * 1024;
    float4 a = *(const float4*)(row + tid * 4);
    float4 b = *(const float4*)(v + tid * 4);
    float p = tanhf(a.x) * b.x + tanhf(a.y) * b.y + tanhf(a.z) * b.z + tanhf(a.w) * b.w;
#pragma unroll
    for (int o = 16; o; o >>= 1) p += __shfl_xor_sync(0xffffffffu, p, o);
    if ((tid & 31) == 0) red[tid >> 5] = p;
    __syncthreads();
    if (tid < 32) {
        p = (tid < 8) ? red[tid] : 0.f;
#pragma unroll
        for (int o = 4; o; o >>= 1) p += __shfl_xor_sync(0xffffffffu, p, o);
        if (tid == 0) s[(long long)k * LSEQ + l] = p;
    }
}

// out fp32 always; optional hi/lo
__global__ void __launch_bounds__(256) fuse_combine_kernel(
    const float* __restrict__ h0, const float* __restrict__ h1,
    const float* __restrict__ s, float* __restrict__ out,
    __nv_bfloat16* __restrict__ outh, __nv_bfloat16* __restrict__ outl)
{
    int l = blockIdx.x, tid = threadIdx.x;
    float s0 = s[l], s1 = s[LSEQ + l];
    float mm = fmaxf(s0, s1);
    float e0 = __expf(s0 - mm), e1 = __expf(s1 - mm);
    float inv = 1.f / (e0 + e1);
    float w0 = e0 * inv, w1 = e1 * inv;
    float4 a = *(const float4*)(h0 + (long long)l * 1024 + tid * 4);
    float4 b = *(const float4*)(h1 + (long long)l * 1024 + tid * 4);
    float4 o;
    o.x = w0 * a.x + w1 * b.x; o.y = w0 * a.y + w1 * b.y;
    o.z = w0 * a.z + w1 * b.z; o.w = w0 * a.w + w1 * b.w;
    long long ob = (long long)l * 1024 + tid * 4;
    *(float4*)(out + ob) = o;
    if (outh) {
        __nv_bfloat16 x0, y0, x1, y1;
        split_bf16(o.x, x0, y0); split_bf16(o.y, x1, y1);
        *(__nv_bfloat162*)(outh + ob) = __nv_bfloat162(x0, x1);
        *(__nv_bfloat162*)(outl + ob) = __nv_bfloat162(y0, y1);
        split_bf16(o.z, x0, y0); split_bf16(o.w, x1, y1);
        *(__nv_bfloat162*)(outh + ob + 2) = __nv_bfloat162(x0, x1);
        *(__nv_bfloat162*)(outl + ob + 2) = __nv_bfloat162(y0, y1);
    }
}

// ===================== classifier + log_softmax =====================
__global__ void __launch_bounds__(256) classify_kernel(
    const float* __restrict__ x, const float* __restrict__ Wc,
    const float* __restrict__ bc, float* __restrict__ out)
{
    __shared__ float red[8][8];
    int l = blockIdx.x, tid = threadIdx.x;
    const float* row = x + (long long)l * 1024;
    float p[NCLS];
#pragma unroll
    for (int c = 0; c < NCLS; c++) p[c] = 0.f;
    for (int d = tid; d < 1024; d += 256) {
        float xv = row[d];
#pragma unroll
        for (int c = 0; c < NCLS; c++) p[c] += xv * Wc[d * NCLS + c];
    }
#pragma unroll
    for (int c = 0; c < NCLS; c++)
#pragma unroll
        for (int o = 16; o; o >>= 1) p[c] += __shfl_xor_sync(0xffffffffu, p[c], o);
    if ((tid & 31) == 0)
#pragma unroll
        for (int c = 0; c < NCLS; c++) red[tid >> 5][c] = p[c];
    __syncthreads();
    if (tid == 0) {
        float lg[NCLS];
#pragma unroll
        for (int c = 0; c < NCLS; c++) {
            float a = bc[c];
#pragma unroll
            for (int w = 0; w < 8; w++) a += red[w][c];
            lg[c] = a;
        }
        float mm = lg[0];
#pragma unroll
        for (int c = 1; c < NCLS; c++) mm = fmaxf(mm, lg[c]);
        float se = 0.f;
#pragma unroll
        for (int c = 0; c < NCLS; c++) se += expf(lg[c] - mm);
        float lse = mm + logf(se);
#pragma unroll
        for (int c = 0; c < NCLS; c++) out[(long long)l * NCLS + c] = lg[c] - lse;
    }
}

// ===================== orchestration =====================
extern "C" void kernel_launch(void* const* d_in, const int* in_sizes, int n_in,
                              void* d_out, int out_size)
{
    const float* src  = (const float*)d_in[0];
    const int*   utt  = (const int*)d_in[1];
    const int*   spk  = (const int*)d_in[2];
    const int*   win  = (const int*)d_in[3];
    const float* Wqkv = (const float*)d_in[4];
    const float* bqkv = (const float*)d_in[5];
    const float* Wo   = (const float*)d_in[6];
    const float* bo   = (const float*)d_in[7];
    const float* ln1g = (const float*)d_in[8];
    const float* ln1b = (const float*)d_in[9];
    const float* Wf1  = (const float*)d_in[10];
    const float* bf1  = (const float*)d_in[11];
    const float* Wf2  = (const float*)d_in[12];
    const float* bf2  = (const float*)d_in[13];
    const float* ln2g = (const float*)d_in[14];
    const float* ln2b = (const float*)d_in[15];
    const float* f1W  = (const float*)d_in[16];
    const float* f1b  = (const float*)d_in[17];
    const float* f1v  = (const float*)d_in[18];
    const float* f2W  = (const float*)d_in[19];
    const float* f2b  = (const float*)d_in[20];
    const float* f2v  = (const float*)d_in[21];
    const float* clsW = (const float*)d_in[22];
    const float* clsb = (const float*)d_in[23];

    float *x, *qkv, *t2, *t1f, *sc, *sp, *fo;
    cudaGetSymbolAddress((void**)&x,    g_x);
    cudaGetSymbolAddress((void**)&qkv,  g_qkv);
    cudaGetSymbolAddress((void**)&t2,   g_t2);
    cudaGetSymbolAddress((void**)&t1f,  g_t1f);
    cudaGetSymbolAddress((void**)&sc,   g_sc);
    cudaGetSymbolAddress((void**)&sp,   g_sp);
    cudaGetSymbolAddress((void**)&fo,   g_fo);

    __nv_bfloat16 *xh, *xl, *ah, *al, *t1h, *t1l, *sph, *spl;
    cudaGetSymbolAddress((void**)&xh,  g_xh);
    cudaGetSymbolAddress((void**)&xl,  g_xl);
    cudaGetSymbolAddress((void**)&ah,  g_ah);
    cudaGetSymbolAddress((void**)&al,  g_al);
    cudaGetSymbolAddress((void**)&t1h, g_t1h);
    cudaGetSymbolAddress((void**)&t1l, g_t1l);
    cudaGetSymbolAddress((void**)&sph, g_sph);
    cudaGetSymbolAddress((void**)&spl, g_spl);

    __nv_bfloat16 *wqkvTh, *wqkvTl, *woTh, *woTl, *wf1Th, *wf1Tl, *wf2Th, *wf2Tl;
    __nv_bfloat16 *f1wTh, *f1wTl, *f2wTh, *f2wTl;
    cudaGetSymbolAddress((void**)&wqkvTh, g_wqkvT_h);
    cudaGetSymbolAddress((void**)&wqkvTl, g_wqkvT_l);
    cudaGetSymbolAddress((void**)&woTh,   g_woT_h);
    cudaGetSymbolAddress((void**)&woTl,   g_woT_l);
    cudaGetSymbolAddress((void**)&wf1Th,  g_wf1T_h);
    cudaGetSymbolAddress((void**)&wf1Tl,  g_wf1T_l);
    cudaGetSymbolAddress((void**)&wf2Th,  g_wf2T_h);
    cudaGetSymbolAddress((void**)&wf2Tl,  g_wf2T_l);
    cudaGetSymbolAddress((void**)&f1wTh,  g_f1wT_h);
    cudaGetSymbolAddress((void**)&f1wTl,  g_f1wT_l);
    cudaGetSymbolAddress((void**)&f2wTh,  g_f2wT_h);
    cudaGetSymbolAddress((void**)&f2wTl,  g_f2wT_l);

    cudaFuncSetAttribute(hmma_gemm_kernel, cudaFuncAttributeMaxDynamicSharedMemorySize,
                         GEMM_SMEM_BYTES);

    const long long LD = (long long)LSEQ * DMODEL;
    dim3 tb(32, 8);

    // 4 big weight transposes + add_pe = 5 launches; launch #6 is the QKV GEMM
    // (so ncu -s 5 -c 1 captures a GEMM, not a transpose).
    transpose_split_kernel<<<dim3(96, 32, 9),   tb>>>(Wqkv, wqkvTh, wqkvTl, 1024, 3072);
    transpose_split_kernel<<<dim3(32, 32, 9),   tb>>>(Wo,   woTh,   woTl,   1024, 1024);
    transpose_split_kernel<<<dim3(128, 32, 9),  tb>>>(Wf1,  wf1Th,  wf1Tl,  1024, 4096);
    transpose_split_kernel<<<dim3(32, 128, 9),  tb>>>(Wf2,  wf2Th,  wf2Tl,  4096, 1024);
    add_pe_kernel<<<LSEQ * DMODEL / 256, 256>>>(src, x, xh, xl);

    for (int l = 0; l < NLAYER; l++) {
        // QKV: fp32 out (attention consumes fp32)
        hmma_gemm_kernel<<<dim3(24, 8, 3), 256, GEMM_SMEM_BYTES>>>(
            xh, xl, LD,
            wqkvTh + (long long)l * 3072 * 1024, wqkvTl + (long long)l * 3072 * 1024,
            (long long)NLAYER * 3072 * 1024,
            bqkv + (long long)l * 3072, (long long)NLAYER * 3072,
            qkv, nullptr, nullptr, (long long)LSEQ * 3072, 3072, 1024, 2);

        attn_kernel<<<dim3(LSEQ / 64, NHEADS, 3), 256>>>(qkv, ah, al, utt, spk, win);

        // Wo: A = attn hi/lo, fp32 out (residual add)
        hmma_gemm_kernel<<<dim3(8, 8, 3), 256, GEMM_SMEM_BYTES>>>(
            ah, al, LD,
            woTh + (long long)l * 1024 * 1024, woTl + (long long)l * 1024 * 1024,
            (long long)NLAYER * 1024 * 1024,
            bo + (long long)l * 1024, (long long)NLAYER * 1024,
            t2, nullptr, nullptr, LD, 1024, 1024, 2);

        add_ln_kernel<<<3 * LSEQ, 256>>>(x, xh, xl, t2, ln1g, ln1b, l);

        // FF1: relu + bf16 hi/lo out only (FF2 is the sole consumer)
        hmma_gemm_kernel<<<dim3(32, 8, 3), 256, GEMM_SMEM_BYTES>>>(
            xh, xl, LD,
            wf1Th + (long long)l * 4096 * 1024, wf1Tl + (long long)l * 4096 * 1024,
            (long long)NLAYER * 4096 * 1024,
            bf1 + (long long)l * 4096, (long long)NLAYER * 4096,
            nullptr, t1h, t1l, (long long)LSEQ * 4096, 4096, 1024, 1 | 4);

        // FF2: fp32 out (residual add)
        hmma_gemm_kernel<<<dim3(8, 8, 3), 256, GEMM_SMEM_BYTES>>>(
            t1h, t1l, (long long)LSEQ * 4096,
            wf2Th + (long long)l * 1024 * 4096, wf2Tl + (long long)l * 1024 * 4096,
            (long long)NLAYER * 1024 * 4096,
            bf2 + (long long)l * 1024, (long long)NLAYER * 1024,
            t2, nullptr, nullptr, LD, 1024, 4096, 2);

        add_ln_kernel<<<3 * LSEQ, 256>>>(x, xh, xl, t2, ln2g, ln2b, l);
    }

    // fusion weight transposes (deferred to keep early launch order GEMM-friendly)
    transpose_split_kernel<<<dim3(32, 32, 1), tb>>>(f1W, f1wTh, f1wTl, 1024, 1024);
    transpose_split_kernel<<<dim3(32, 32, 1), tb>>>(f2W, f2wTh, f2wTl, 1024, 1024);

    // fusion 1: branches sm (z=1), om (z=2)
    hmma_gemm_kernel<<<dim3(8, 8, 2), 256, GEMM_SMEM_BYTES>>>(
        xh + LD, xl + LD, LD, f1wTh, f1wTl, 0, f1b, 0,
        t1f, nullptr, nullptr, LD, 1024, 1024, 2);
    fuse_score_kernel<<<dim3(LSEQ, 2), 256>>>(t1f, f1v, sc);
    fuse_combine_kernel<<<LSEQ, 256>>>(x + LD, x + 2 * LD, sc, sp, sph, spl);

    // fusion 2: ct (x branch 0), sp
    hmma_gemm_kernel<<<dim3(8, 8, 1), 256, GEMM_SMEM_BYTES>>>(
        xh, xl, 0, f2wTh, f2wTl, 0, f2b, 0,
        t1f, nullptr, nullptr, 0, 1024, 1024, 2);
    hmma_gemm_kernel<<<dim3(8, 8, 1), 256, GEMM_SMEM_BYTES>>>(
        sph, spl, 0, f2wTh, f2wTl, 0, f2b, 0,
        t1f + LD, nullptr, nullptr, 0, 1024, 1024, 2);
    fuse_score_kernel<<<dim3(LSEQ, 2), 256>>>(t1f, f2v, sc);
    fuse_combine_kernel<<<LSEQ, 256>>>(x, sp, sc, fo, nullptr, nullptr);

    classify_kernel<<<LSEQ, 256>>>(fo, clsW, clsb, (float*)d_out);
}